// round 2
// baseline (speedup 1.0000x reference)
#include <cuda_runtime.h>

#define NSTEPS   730
#define NGRID    8000
#define HALF     4000        // cells per thread-lane set; thread handles g and g+HALF
#define UHL      15
#define UNR      5           // 730 = 146 * 5, exact
#define NEARZERO 1e-5f

__device__ __forceinline__ float sigmoidf_(float x) {
    return 1.0f / (1.0f + __expf(-x));
}

__global__ __launch_bounds__(32, 1)
void hbv_kernel(const float* __restrict__ xphy,    // [T, G, 3]
                const float* __restrict__ params,  // [T, G, 16]
                float*       __restrict__ out)     // [T, G, 4]
{
    const int gA = blockIdx.x * 32 + threadIdx.x;   // cell 0
    if (gA >= HALF) return;
    // cell indices for the two independent chains this thread owns
    int gi[2];
    gi[0] = gA;
    gi[1] = gA + HALF;

    // ---------------- per-cell parameters ----------------
    float pBETA[2], pFC[2], invfc[2], pK0[2], pK1[2], pK2[2], invlpfc[2];
    float pPERC[2], pUZL[2], pTT[2], pCFMAX[2], cfrcf[2], pCWH[2], pBETAET[2], pC[2];
    float w[2][UHL];

    #pragma unroll
    for (int c = 0; c < 2; c++) {
        const float* pr = params + ((size_t)(NSTEPS - 1) * NGRID + (size_t)gi[c]) * 16;
        float4 r0 = *(const float4*)(pr + 0);
        float4 r1 = *(const float4*)(pr + 4);
        float4 r2 = *(const float4*)(pr + 8);
        float4 r3 = *(const float4*)(pr + 12);

        pBETA[c]  = 1.0f   + sigmoidf_(r0.x) * 5.0f;
        pFC[c]    = 50.0f  + sigmoidf_(r0.y) * 950.0f;
        pK0[c]    = 0.05f  + sigmoidf_(r0.z) * 0.85f;
        pK1[c]    = 0.01f  + sigmoidf_(r0.w) * 0.49f;
        pK2[c]    = 0.001f + sigmoidf_(r1.x) * 0.199f;
        float pLP = 0.2f   + sigmoidf_(r1.y) * 0.8f;
        pPERC[c]  =          sigmoidf_(r1.z) * 10.0f;
        pUZL[c]   =          sigmoidf_(r1.w) * 100.0f;
        pTT[c]    = -2.5f  + sigmoidf_(r2.x) * 5.0f;
        pCFMAX[c] = 0.5f   + sigmoidf_(r2.y) * 9.5f;
        cfrcf[c]  =          sigmoidf_(r2.z) * 0.1f * pCFMAX[c];
        pCWH[c]   =          sigmoidf_(r2.w) * 0.2f;
        pBETAET[c]= 0.3f   + sigmoidf_(r3.x) * 4.7f;
        pC[c]     =          sigmoidf_(r3.y);
        float route_a =      sigmoidf_(r3.z) * 2.9f;
        float route_b =      sigmoidf_(r3.w) * 6.5f;

        invfc[c]   = __fdividef(1.0f, pFC[c]);
        invlpfc[c] = __fdividef(1.0f, pLP * pFC[c]);

        // gamma UH weights; Gamma(a)*theta^a cancels in normalization
        const float aa    = fmaxf(route_a, 0.0f) + 0.1f;
        const float theta = fmaxf(route_b, 0.0f) + 0.5f;
        const float am1   = aa - 1.0f;
        const float invth = __fdividef(1.0f, theta);
        float wsum = 0.0f;
        #pragma unroll
        for (int k = 0; k < UHL; k++) {
            float tk = (float)k + 0.5f;
            float v  = __expf(am1 * __logf(tk) - tk * invth);
            w[c][k] = v;
            wsum += v;
        }
        const float inv_wsum = __fdividef(1.0f, wsum);
        #pragma unroll
        for (int k = 0; k < UHL; k++) w[c][k] *= inv_wsum;
    }

    // ---------------- state ----------------
    float SNOWPACK[2], MELTWATER[2], SM[2], SUZ[2], SLZ[2];
    float a0[2][UHL - 1], a1[2][UHL - 1], a2[2][UHL - 1];
    #pragma unroll
    for (int c = 0; c < 2; c++) {
        SNOWPACK[c] = 0.001f; MELTWATER[c] = 0.001f; SM[c] = 0.001f;
        SUZ[c] = 0.001f; SLZ[c] = 0.001f;
        #pragma unroll
        for (int j = 0; j < UHL - 1; j++) { a0[c][j] = 0.0f; a1[c][j] = 0.0f; a2[c][j] = 0.0f; }
    }

    // ---------------- rolling input prefetch (distance = UNR steps) ----------
    float buf[2][UNR][3];
    #pragma unroll
    for (int c = 0; c < 2; c++)
        #pragma unroll
        for (int u = 0; u < UNR; u++) {
            size_t idx = ((size_t)u * NGRID + (size_t)gi[c]) * 3;
            buf[c][u][0] = xphy[idx + 0];
            buf[c][u][1] = xphy[idx + 1];
            buf[c][u][2] = xphy[idx + 2];
        }

    float4* __restrict__ out4 = (float4*)out;

    for (int tb = 0; tb < NSTEPS; tb += UNR) {
        #pragma unroll
        for (int u = 0; u < UNR; u++) {
            const int t = tb + u;
            float y0v[2], y1v[2], y2v[2];

            #pragma unroll
            for (int c = 0; c < 2; c++) {
                const float P   = buf[c][u][0];
                const float Tt  = buf[c][u][1];
                const float PET = buf[c][u][2];

                // refill this slot with step t+UNR (prefetch distance UNR)
                if (t + UNR < NSTEPS) {
                    size_t idx = ((size_t)(t + UNR) * NGRID + (size_t)gi[c]) * 3;
                    buf[c][u][0] = xphy[idx + 0];
                    buf[c][u][1] = xphy[idx + 1];
                    buf[c][u][2] = xphy[idx + 2];
                }

                // ---- start SM critical chain immediately ----
                const float sw = fminf(__expf(pBETA[c] * __logf(SM[c] * invfc[c])), 1.0f);

                // ---- snow chain (independent of SM chain) ----
                const float RAIN = (Tt >= pTT[c]) ? P : 0.0f;
                const float SNOW = (Tt <  pTT[c]) ? P : 0.0f;
                float sp = SNOWPACK[c] + SNOW;
                const float melt = fminf(fmaxf(pCFMAX[c] * (Tt - pTT[c]), 0.0f), sp);
                float mw = MELTWATER[c] + melt;
                sp -= melt;
                const float refreeze = fminf(fmaxf(cfrcf[c] * (pTT[c] - Tt), 0.0f), mw);
                sp += refreeze;
                mw -= refreeze;
                const float tosoil = fmaxf(mw - pCWH[c] * sp, 0.0f);
                mw -= tosoil;
                SNOWPACK[c] = sp;
                MELTWATER[c] = mw;

                // ---- soil moisture ----
                const float rt  = RAIN + tosoil;
                const float smrt = SM[c] + rt;
                const float recharge = rt * sw;
                const float SM1 = fmaf(-rt, sw, smrt);           // SM + rt - recharge
                const float excess = fmaxf(SM1 - pFC[c], 0.0f);  // parallel branch
                const float SM2 = fminf(SM1, pFC[c]);            // chain branch
                // capillary: min-with-SLZ provably redundant (C<=1, SM2<=FC)
                const float cap = (pC[c] * SLZ[c]) * fmaf(-invfc[c], SM2, 1.0f);
                const float SM3  = fmaxf(SM2 + cap, NEARZERO);
                const float SLZa = fmaxf(SLZ[c] - cap, NEARZERO);

                // ---- evapotranspiration ----
                const float evr = fminf(SM3 * invlpfc[c], 1.0f); // SM3>0 so no low clip
                const float ef  = __expf(pBETAET[c] * __logf(evr));
                const float ET  = fminf(PET * ef, SM3);
                SM[c] = fmaxf(SM3 - ET, NEARZERO);

                // ---- response routine ----
                float suz = SUZ[c] + recharge + excess;
                const float perc = fminf(suz, pPERC[c]);
                suz -= perc;
                const float Q0 = pK0[c] * fmaxf(suz - pUZL[c], 0.0f);
                suz -= Q0;
                const float Q1 = pK1[c] * suz;
                SUZ[c] = suz - Q1;
                float slz = SLZa + perc;
                const float Q2 = pK2[c] * slz;
                SLZ[c] = slz - Q2;

                // ---- 15-tap causal conv (shift-FMA accumulators) ----
                y0v[c] = a0[c][0] + w[c][0] * Q0;
                y1v[c] = a1[c][0] + w[c][0] * Q1;
                y2v[c] = a2[c][0] + w[c][0] * Q2;
                #pragma unroll
                for (int j = 0; j < UHL - 2; j++) {
                    a0[c][j] = a0[c][j + 1] + w[c][j + 1] * Q0;
                    a1[c][j] = a1[c][j + 1] + w[c][j + 1] * Q1;
                    a2[c][j] = a2[c][j + 1] + w[c][j + 1] * Q2;
                }
                a0[c][UHL - 2] = w[c][UHL - 1] * Q0;
                a1[c][UHL - 2] = w[c][UHL - 1] * Q1;
                a2[c][UHL - 2] = w[c][UHL - 1] * Q2;
            }

            // ---- stores (both cells) ----
            #pragma unroll
            for (int c = 0; c < 2; c++) {
                float4 o;
                o.x = y0v[c] + y1v[c] + y2v[c];
                o.y = y0v[c];
                o.z = y1v[c];
                o.w = y2v[c];
                out4[(size_t)t * NGRID + (size_t)gi[c]] = o;
            }
        }
    }
}

extern "C" void kernel_launch(void* const* d_in, const int* in_sizes, int n_in,
                              void* d_out, int out_size) {
    const float* xphy   = (const float*)d_in[0];   // [730, 8000, 3]
    const float* params = (const float*)d_in[1];   // [730, 8000, 16]
    float* out = (float*)d_out;                    // [730, 8000, 4]
    (void)in_sizes; (void)n_in; (void)out_size;

    dim3 block(32);
    dim3 grid(HALF / 32);   // 125 blocks, one warp each
    hbv_kernel<<<grid, block>>>(xphy, params, out);
}

// round 4
// speedup vs baseline: 1.2638x; 1.2638x over previous
#include <cuda_runtime.h>
#include <cstdint>

#define NSTEPS   730
#define NGRID    8000
#define UHL      15
#define CH       10          // timesteps per smem chunk; 730 = 73 * 10
#define BT       64          // threads (cells) per block
#define NCHUNK   (NSTEPS / CH)
#define NEARZERO 1e-5f

__device__ __forceinline__ float sigmoidf_(float x) {
    return 1.0f / (1.0f + __expf(-x));
}

__device__ __forceinline__ uint32_t smem_u32(const void* p) {
    uint32_t a;
    asm("{ .reg .u64 t; cvta.to.shared.u64 t, %1; cvt.u32.u64 %0, t; }" : "=r"(a) : "l"(p));
    return a;
}

__device__ __forceinline__ void cp_async16(uint32_t dst, const void* src) {
    asm volatile("cp.async.ca.shared.global [%0], [%1], 16;\n" :: "r"(dst), "l"(src));
}
__device__ __forceinline__ void cp_commit() {
    asm volatile("cp.async.commit_group;\n");
}
__device__ __forceinline__ void cp_wait1() {
    asm volatile("cp.async.wait_group 1;\n");
}

// smem staging: [2 buffers][CH timesteps][BT cells * 3 vars]
__shared__ float sbuf[2][CH][BT * 3];

// issue async copy of chunk `c` into buffer `pb` (cooperative, 16B ops)
__device__ __forceinline__ void issue_chunk(const float* __restrict__ xphy,
                                            int c, int pb, int g0, int tid,
                                            uint32_t sbase) {
    const int t0 = c * CH;
    const float* src_base = xphy + (size_t)t0 * (NGRID * 3) + (size_t)g0 * 3;
    // CH rows, each BT*3 floats = BT*3/4 16B chunks per row
    constexpr int ROW16 = BT * 3 / 4;        // 48
    constexpr int TOT16 = CH * ROW16;        // 480
    #pragma unroll 1
    for (int idx = tid; idx < TOT16; idx += BT) {
        int row = idx / ROW16;
        int col = idx - row * ROW16;         // 16B units within row
        const float* src = src_base + (size_t)row * (NGRID * 3) + col * 4;
        uint32_t dst = sbase + (uint32_t)(((pb * CH + row) * (BT * 3) + col * 4) * 4);
        cp_async16(dst, src);
    }
    cp_commit();
}

__global__ __launch_bounds__(BT, 1)
void hbv_kernel(const float* __restrict__ xphy,    // [T, G, 3]
                const float* __restrict__ params,  // [T, G, 16]
                float*       __restrict__ out)     // [T, G, 4]
{
    const int tid = threadIdx.x;
    const int g0  = blockIdx.x * BT;
    const int g   = g0 + tid;
    const uint32_t sbase = smem_u32(&sbuf[0][0][0]);

    // ---------------- static parameters (last timestep only) ----------------
    const float* pr = params + ((size_t)(NSTEPS - 1) * NGRID + (size_t)g) * 16;
    float4 r0 = *(const float4*)(pr + 0);
    float4 r1 = *(const float4*)(pr + 4);
    float4 r2 = *(const float4*)(pr + 8);
    float4 r3 = *(const float4*)(pr + 12);

    const float parBETA   = 1.0f   + sigmoidf_(r0.x) * 5.0f;
    const float parFC     = 50.0f  + sigmoidf_(r0.y) * 950.0f;
    const float parK0     = 0.05f  + sigmoidf_(r0.z) * 0.85f;
    const float parK1     = 0.01f  + sigmoidf_(r0.w) * 0.49f;
    const float parK2     = 0.001f + sigmoidf_(r1.x) * 0.199f;
    const float parLP     = 0.2f   + sigmoidf_(r1.y) * 0.8f;
    const float parPERC   =          sigmoidf_(r1.z) * 10.0f;
    const float parUZL    =          sigmoidf_(r1.w) * 100.0f;
    const float parTT     = -2.5f  + sigmoidf_(r2.x) * 5.0f;
    const float parCFMAX  = 0.5f   + sigmoidf_(r2.y) * 9.5f;
    const float cfr_cfmax =          sigmoidf_(r2.z) * 0.1f * parCFMAX;
    const float parCWH    =          sigmoidf_(r2.w) * 0.2f;
    const float parBETAET = 0.3f   + sigmoidf_(r3.x) * 4.7f;
    const float parC      =          sigmoidf_(r3.y);
    const float route_a   =          sigmoidf_(r3.z) * 2.9f;
    const float route_b   =          sigmoidf_(r3.w) * 6.5f;

    const float inv_fc   = __fdividef(1.0f, parFC);
    const float inv_lpfc = __fdividef(1.0f, parLP * parFC);

    // gamma UH weights; Gamma(a)*theta^a cancels in normalization
    const float aa    = fmaxf(route_a, 0.0f) + 0.1f;
    const float theta = fmaxf(route_b, 0.0f) + 0.5f;
    const float am1   = aa - 1.0f;
    const float invth = __fdividef(1.0f, theta);

    float w[UHL];
    float wsum = 0.0f;
    #pragma unroll
    for (int k = 0; k < UHL; k++) {
        float tk = (float)k + 0.5f;
        float v  = __expf(am1 * __logf(tk) - tk * invth);
        w[k] = v;
        wsum += v;
    }
    const float inv_wsum = __fdividef(1.0f, wsum);
    #pragma unroll
    for (int k = 0; k < UHL; k++) w[k] *= inv_wsum;

    // ---------------- state ----------------
    float SNOWPACK = 0.001f, MELTWATER = 0.001f, SM = 0.001f, SUZ = 0.001f, SLZ = 0.001f;
    float a0[UHL - 1], a1[UHL - 1], a2[UHL - 1];
    #pragma unroll
    for (int j = 0; j < UHL - 1; j++) { a0[j] = 0.0f; a1[j] = 0.0f; a2[j] = 0.0f; }

    // prologue: issue chunks 0 and 1
    issue_chunk(xphy, 0, 0, g0, tid, sbase);
    issue_chunk(xphy, 1, 1, g0, tid, sbase);

    float4* __restrict__ outp = (float4*)out + g;   // advance by NGRID per step
    const int s3 = tid * 3;

    for (int k = 0; k < NCHUNK; k++) {
        const int pb = k & 1;
        cp_wait1();            // chunk k complete (<=1 group in flight)
        __syncthreads();       // copies done by other threads now visible

        #pragma unroll
        for (int u = 0; u < CH; u++) {
            const float P   = sbuf[pb][u][s3 + 0];
            const float Tt  = sbuf[pb][u][s3 + 1];
            const float PET = sbuf[pb][u][s3 + 2];

            // ---- SM critical chain starts immediately ----
            const float sw = fminf(__expf(parBETA * __logf(SM * inv_fc)), 1.0f);

            // ---- snow (parallel branch) ----
            const float RAIN = (Tt >= parTT) ? P : 0.0f;
            const float SNOW = (Tt <  parTT) ? P : 0.0f;
            float sp = SNOWPACK + SNOW;
            const float melt = fminf(fmaxf(parCFMAX * (Tt - parTT), 0.0f), sp);
            float mw = MELTWATER + melt;
            sp -= melt;
            const float refreeze = fminf(fmaxf(cfr_cfmax * (parTT - Tt), 0.0f), mw);
            sp += refreeze;
            mw -= refreeze;
            const float tosoil = fmaxf(mw - parCWH * sp, 0.0f);
            MELTWATER = mw - tosoil;
            SNOWPACK  = sp;

            // ---- soil moisture ----
            const float rt   = RAIN + tosoil;
            const float smrt = SM + rt;
            const float recharge = rt * sw;
            const float SM1 = fmaf(-rt, sw, smrt);
            const float excess = fmaxf(SM1 - parFC, 0.0f);
            const float SM2 = fminf(SM1, parFC);
            // capillary (min-with-SLZ redundant: C<=1 and SM2<=FC)
            const float cSLZ = parC * SLZ;                       // off-chain
            const float cap  = cSLZ * fmaf(-inv_fc, SM2, 1.0f);
            const float SM3  = fmaxf(SM2 + cap, NEARZERO);
            const float SLZa = fmaxf(SLZ - cap, NEARZERO);

            // ---- evapotranspiration ----
            const float evr = fminf(SM3 * inv_lpfc, 1.0f);
            const float ef  = __expf(parBETAET * __logf(evr));
            const float ET  = fminf(PET * ef, SM3);
            SM = fmaxf(SM3 - ET, NEARZERO);

            // ---- response routine ----
            float suz = SUZ + recharge + excess;
            const float perc = fminf(suz, parPERC);
            suz -= perc;
            const float Q0 = parK0 * fmaxf(suz - parUZL, 0.0f);
            suz -= Q0;
            const float Q1 = parK1 * suz;
            SUZ = suz - Q1;
            float slz = SLZa + perc;
            const float Q2 = parK2 * slz;
            SLZ = slz - Q2;

            // ---- 15-tap causal conv via shift-FMA accumulators ----
            const float y0 = a0[0] + w[0] * Q0;
            const float y1 = a1[0] + w[0] * Q1;
            const float y2 = a2[0] + w[0] * Q2;
            #pragma unroll
            for (int j = 0; j < UHL - 2; j++) {
                a0[j] = a0[j + 1] + w[j + 1] * Q0;
                a1[j] = a1[j + 1] + w[j + 1] * Q1;
                a2[j] = a2[j + 1] + w[j + 1] * Q2;
            }
            a0[UHL - 2] = w[UHL - 1] * Q0;
            a1[UHL - 2] = w[UHL - 1] * Q1;
            a2[UHL - 2] = w[UHL - 1] * Q2;

            float4 o;
            o.x = y0 + y1 + y2;
            o.y = y0;
            o.z = y1;
            o.w = y2;
            *outp = o;
            outp += NGRID;
        }

        __syncthreads();       // everyone done reading buffer pb
        if (k + 2 < NCHUNK)
            issue_chunk(xphy, k + 2, pb, g0, tid, sbase);  // overwrite pb
        else
            cp_commit();       // keep group accounting consistent
    }
}

extern "C" void kernel_launch(void* const* d_in, const int* in_sizes, int n_in,
                              void* d_out, int out_size) {
    const float* xphy   = (const float*)d_in[0];   // [730, 8000, 3]
    const float* params = (const float*)d_in[1];   // [730, 8000, 16]
    float* out = (float*)d_out;                    // [730, 8000, 4]
    (void)in_sizes; (void)n_in; (void)out_size;

    dim3 block(BT);
    dim3 grid(NGRID / BT);   // 125 blocks x 2 warps
    hbv_kernel<<<grid, block>>>(xphy, params, out);
}